// round 9
// baseline (speedup 1.0000x reference)
#include <cuda_runtime.h>
#include <cuda_fp16.h>
#include <stdint.h>

// ---------------- problem constants ----------------
constexpr int kE   = 8;
constexpr int kH   = 1024;
constexpr int kF   = 4096;
constexpr int kDL  = 256;
constexpr int kTPE = 1024;
constexpr int kTok = kE * kTPE;   // 8192

// ---------------- tiling: 128x128 CTAs, 8 warps, 2 CTAs/SM ----------------
constexpr int BM = 128, BN = 128, BK = 64;
constexpr int THREADS = 256;      // 8 warps: 4 (M) x 2 (N), warp tile 32x64
constexpr int ST1 = 3;
constexpr int ST3 = 3;

constexpr int LDSA  = BK + 8;     // 72 halves per A row
constexpr int LDSB  = BK + 8;     // 72 halves per B row (NT: [n][k])
constexpr int LDSB3 = BN + 8;     // 136 halves per B row (NN: [k][n])

constexpr int STG12 = BM * LDSA + BN * LDSB;   // 18432 halves / stage
constexpr int STG3  = BM * LDSA + BK * LDSB3;  // 17920 halves / stage
constexpr int SMEM12 = ST1 * STG12 * 2;        // 110592 B (x2 CTA/SM)
constexpr int SMEM3  = ST3 * STG3  * 2;        // 107520 B (x2 CTA/SM)

// ---------------- fp16 scratch (device globals) ----------------
__device__ __half g_xh [(size_t)kTok * kH];        // 16 MB
__device__ __half g_ah [(size_t)kTok * kDL];       //  4 MB
__device__ __half g_hh [(size_t)kTok * kF];        // 64 MB (x1 then silu(x1)*x2)

// ---------------- PTX helpers ----------------
__device__ __forceinline__ uint32_t smem_u32(const void* p) {
    uint32_t r;
    asm volatile("{ .reg .u64 t; cvta.to.shared.u64 t, %1; cvt.u32.u64 %0, t; }"
                 : "=r"(r) : "l"(p));
    return r;
}
__device__ __forceinline__ void cp16(uint32_t dst, const void* src) {
    asm volatile("cp.async.cg.shared.global [%0], [%1], 16;" :: "r"(dst), "l"(src));
}
__device__ __forceinline__ void cp_commit() { asm volatile("cp.async.commit_group;"); }
template <int N> __device__ __forceinline__ void cp_wait() {
    asm volatile("cp.async.wait_group %0;" :: "n"(N));
}
__device__ __forceinline__ void ldsm4(uint32_t* r, uint32_t a) {
    asm volatile("ldmatrix.sync.aligned.m8n8.x4.shared.b16 {%0,%1,%2,%3},[%4];"
                 : "=r"(r[0]), "=r"(r[1]), "=r"(r[2]), "=r"(r[3]) : "r"(a));
}
__device__ __forceinline__ void ldsm4t(uint32_t* r, uint32_t a) {
    asm volatile("ldmatrix.sync.aligned.m8n8.x4.trans.shared.b16 {%0,%1,%2,%3},[%4];"
                 : "=r"(r[0]), "=r"(r[1]), "=r"(r[2]), "=r"(r[3]) : "r"(a));
}
__device__ __forceinline__ void mma16816(float* c, const uint32_t* a, uint32_t b0, uint32_t b1) {
    asm volatile(
        "mma.sync.aligned.m16n8k16.row.col.f32.f16.f16.f32 "
        "{%0,%1,%2,%3},{%4,%5,%6,%7},{%8,%9},{%0,%1,%2,%3};"
        : "+f"(c[0]), "+f"(c[1]), "+f"(c[2]), "+f"(c[3])
        : "r"(a[0]), "r"(a[1]), "r"(a[2]), "r"(a[3]), "r"(b0), "r"(b1));
}

// ---------------- fp32 -> fp16 conversion: x + acts only ----------------
__global__ void k_cvt2(const float* __restrict__ x, const float* __restrict__ a) {
    constexpr size_t N1 = (size_t)kTok * kH / 4, N2 = (size_t)kTok * kDL / 4;
    for (size_t i = (size_t)blockIdx.x * blockDim.x + threadIdx.x; i < N1 + N2;
         i += (size_t)gridDim.x * blockDim.x) {
        const float4* s; __half2* d; size_t o;
        if (i < N1) { s = (const float4*)x; d = (__half2*)g_xh; o = i; }
        else        { s = (const float4*)a; d = (__half2*)g_ah; o = i - N1; }
        float4 t = s[o];
        d[2 * o]     = __floats2half2_rn(t.x, t.y);
        d[2 * o + 1] = __floats2half2_rn(t.z, t.w);
    }
}

// ---------------- A loader: cp.async fp16, 128 rows x 64 halves ----------------
__device__ __forceinline__ void loadA(const __half* gA, int ldA, int kOff,
                                      __half* sA, int tid) {
#pragma unroll
    for (int i = 0; i < 4; i++) {
        int v = tid + i * THREADS;
        int row = v >> 3, c = (v & 7) * 8;
        cp16(smem_u32(sA + row * LDSA + c), gA + (size_t)row * ldA + kOff + c);
    }
}

// ---------------- B fp32 loaders + convert-stores ----------------
// gemm12 NT: B tile = 128 rows x 64 floats (row stride ldB floats)
__device__ __forceinline__ void ldgB_nt(const float* gB, int ldB, int kOff,
                                        float4 (&b)[8], int tid) {
#pragma unroll
    for (int i = 0; i < 4; i++) {
        int v = tid + i * THREADS;
        int row = v >> 3, f = (v & 7) * 8;
        const float4* p = (const float4*)(gB + (size_t)row * ldB + kOff + f);
        b[2 * i] = p[0]; b[2 * i + 1] = p[1];
    }
}
__device__ __forceinline__ void stsB_nt(__half* sB, const float4 (&b)[8], int tid) {
#pragma unroll
    for (int i = 0; i < 4; i++) {
        int v = tid + i * THREADS;
        int row = v >> 3, h = (v & 7) * 8;
        __half2 h4[4] = { __floats2half2_rn(b[2*i].x,   b[2*i].y),
                          __floats2half2_rn(b[2*i].z,   b[2*i].w),
                          __floats2half2_rn(b[2*i+1].x, b[2*i+1].y),
                          __floats2half2_rn(b[2*i+1].z, b[2*i+1].w) };
        *reinterpret_cast<uint4*>(sB + row * LDSB + h) = *reinterpret_cast<uint4*>(h4);
    }
}
// gemm3 NN: B tile = 64 k-rows x 128 n-floats (row stride kH floats)
__device__ __forceinline__ void ldgB_nn(const float* gB, int kOff,
                                        float4 (&b)[8], int tid) {
#pragma unroll
    for (int i = 0; i < 4; i++) {
        int v = tid + i * THREADS;
        int row = v >> 4, f = (v & 15) * 8;
        const float4* p = (const float4*)(gB + (size_t)(kOff + row) * kH + f);
        b[2 * i] = p[0]; b[2 * i + 1] = p[1];
    }
}
__device__ __forceinline__ void stsB_nn(__half* sB, const float4 (&b)[8], int tid) {
#pragma unroll
    for (int i = 0; i < 4; i++) {
        int v = tid + i * THREADS;
        int row = v >> 4, h = (v & 15) * 8;
        __half2 h4[4] = { __floats2half2_rn(b[2*i].x,   b[2*i].y),
                          __floats2half2_rn(b[2*i].z,   b[2*i].w),
                          __floats2half2_rn(b[2*i+1].x, b[2*i+1].y),
                          __floats2half2_rn(b[2*i+1].z, b[2*i+1].w) };
        *reinterpret_cast<uint4*>(sB + row * LDSB3 + h) = *reinterpret_cast<uint4*>(h4);
    }
}

// ---------- software-pipelined warp-tile MMA (32x64), NT variant ----------
__device__ __forceinline__ void mma_nt(const __half* sA, const __half* sB,
                                       float (&acc)[2][8][4], int wm, int wn, int lane) {
    const uint32_t aAddr = smem_u32(sA + (wm * 32 + (lane & 15)) * LDSA + (lane >> 4) * 8);
    const uint32_t bAddr = smem_u32(sB + (wn * 64 + (lane & 7) + ((lane >> 4) << 3)) * LDSB
                                       + ((lane >> 3) & 1) * 8);
    uint32_t a_cur[2][4], a_nxt[2][4], b_cur[4], b_nxt[4];
    ldsm4(a_cur[0], aAddr);
    ldsm4(a_cur[1], aAddr + 16 * LDSA * 2);
    ldsm4(b_cur, bAddr);
#pragma unroll
    for (int k = 0; k < 4; k++) {
#pragma unroll
        for (int j = 0; j < 4; j++) {
            if (j < 3) {
                ldsm4(b_nxt, bAddr + k * 32 + (j + 1) * 16 * LDSB * 2);
            } else if (k < 3) {
                ldsm4(a_nxt[0], aAddr + (k + 1) * 32);
                ldsm4(a_nxt[1], aAddr + (k + 1) * 32 + 16 * LDSA * 2);
                ldsm4(b_nxt, bAddr + (k + 1) * 32);
            }
            mma16816(acc[0][2 * j],     a_cur[0], b_cur[0], b_cur[1]);
            mma16816(acc[1][2 * j],     a_cur[1], b_cur[0], b_cur[1]);
            mma16816(acc[0][2 * j + 1], a_cur[0], b_cur[2], b_cur[3]);
            mma16816(acc[1][2 * j + 1], a_cur[1], b_cur[2], b_cur[3]);
#pragma unroll
            for (int r = 0; r < 4; r++) b_cur[r] = b_nxt[r];
            if (j == 3 && k < 3) {
#pragma unroll
                for (int im = 0; im < 2; im++)
#pragma unroll
                    for (int r = 0; r < 4; r++) a_cur[im][r] = a_nxt[im][r];
            }
        }
    }
}

// ---------- software-pipelined warp-tile MMA (32x64), NN variant ----------
__device__ __forceinline__ void mma_nn(const __half* sA, const __half* sB,
                                       float (&acc)[2][8][4], int wm, int wn, int lane) {
    const uint32_t aAddr = smem_u32(sA + (wm * 32 + (lane & 15)) * LDSA + (lane >> 4) * 8);
    const uint32_t bAddr = smem_u32(sB + ((lane & 7) + ((lane >> 3) & 1) * 8) * LDSB3
                                       + wn * 64 + (lane >> 4) * 8);
    uint32_t a_cur[2][4], a_nxt[2][4], b_cur[4], b_nxt[4];
    ldsm4(a_cur[0], aAddr);
    ldsm4(a_cur[1], aAddr + 16 * LDSA * 2);
    ldsm4t(b_cur, bAddr);
#pragma unroll
    for (int k = 0; k < 4; k++) {
#pragma unroll
        for (int j = 0; j < 4; j++) {
            if (j < 3) {
                ldsm4t(b_nxt, bAddr + k * 16 * LDSB3 * 2 + (j + 1) * 32);
            } else if (k < 3) {
                ldsm4(a_nxt[0], aAddr + (k + 1) * 32);
                ldsm4(a_nxt[1], aAddr + (k + 1) * 32 + 16 * LDSA * 2);
                ldsm4t(b_nxt, bAddr + (k + 1) * 16 * LDSB3 * 2);
            }
            mma16816(acc[0][2 * j],     a_cur[0], b_cur[0], b_cur[1]);
            mma16816(acc[1][2 * j],     a_cur[1], b_cur[0], b_cur[1]);
            mma16816(acc[0][2 * j + 1], a_cur[0], b_cur[2], b_cur[3]);
            mma16816(acc[1][2 * j + 1], a_cur[1], b_cur[2], b_cur[3]);
#pragma unroll
            for (int r = 0; r < 4; r++) b_cur[r] = b_nxt[r];
            if (j == 3 && k < 3) {
#pragma unroll
                for (int im = 0; im < 2; im++)
#pragma unroll
                    for (int r = 0; r < 4; r++) a_cur[im][r] = a_nxt[im][r];
            }
        }
    }
}

// ==================== kernel 1: x1=acts@wup^T, x2=x@v1^T, h=silu(x1)*x2 ===========
__global__ void __launch_bounds__(THREADS, 2) k_gemm12(const float* __restrict__ wupf,
                                                       const float* __restrict__ v1f) {
    extern __shared__ __half smem[];
    const int tid = threadIdx.x, lane = tid & 31, warp = tid >> 5;
    const int wm = warp & 3, wn = warp >> 2;
    const int nt = blockIdx.x, mt = blockIdx.y, e = blockIdx.z;

    const __half* A1 = g_ah + (size_t)(e * kTPE + mt * BM) * kDL;
    const __half* A2 = g_xh + (size_t)(e * kTPE + mt * BM) * kH;
    const float*  B1 = wupf + ((size_t)e * kF + nt * BN) * kDL;
    const float*  B2 = v1f  + ((size_t)e * kF + nt * BN) * kH;

    constexpr int NCH1 = kDL / BK;          // 4
    constexpr int NCH  = NCH1 + kH / BK;    // 20

    auto srcOf = [&](int c, const __half*& A, const float*& B, int& la, int& lb, int& ko) {
        if (c < NCH1) { A = A1; B = B1; la = kDL; lb = kDL; ko = c * BK; }
        else          { A = A2; B = B2; la = kH;  lb = kH;  ko = (c - NCH1) * BK; }
    };

    float acc[2][8][4];
#pragma unroll
    for (int i = 0; i < 2; i++)
#pragma unroll
        for (int j = 0; j < 8; j++)
#pragma unroll
            for (int r = 0; r < 4; r++) acc[i][j][r] = 0.f;

    float4 bb[8];
    // prologue: A via cp.async, B via LDG->cvt->STS for stages 0,1
    {
        const __half* A; const float* B; int la, lb, ko;
#pragma unroll
        for (int c = 0; c < ST1 - 1; c++) {
            srcOf(c, A, B, la, lb, ko);
            __half* sb = smem + c * STG12;
            loadA(A, la, ko, sb, tid);
            cp_commit();
            ldgB_nt(B, lb, ko, bb, tid);
            stsB_nt(sb + BM * LDSA, bb, tid);
        }
    }

    const int rBase = e * kTPE + mt * BM + wm * 32 + (lane >> 2);
    const int cBase = nt * BN + wn * 64 + (lane & 3) * 2;

    for (int kc = 0; kc < NCH; kc++) {
        cp_wait<ST1 - 2>();
        __syncthreads();
        const int pf = kc + ST1 - 1;
        __half* psb = smem + (pf % ST1) * STG12;
        if (pf < NCH) {
            const __half* A; const float* B; int la, lb, ko;
            srcOf(pf, A, B, la, lb, ko);
            loadA(A, la, ko, psb, tid);
            ldgB_nt(B, lb, ko, bb, tid);   // LDG now; STS after mma (latency covered)
        }
        cp_commit();

        if (kc == NCH1) {
            // gemm1 complete: spill raw x1 to g_hh (fp16, thread-private slots), zero acc
#pragma unroll
            for (int i = 0; i < 2; i++)
#pragma unroll
                for (int j = 0; j < 8; j++)
#pragma unroll
                    for (int p = 0; p < 2; p++) {
                        int r = rBase + i * 16 + p * 8;
                        int c = cBase + j * 8;
                        __half2 x1h = __floats2half2_rn(acc[i][j][2 * p], acc[i][j][2 * p + 1]);
                        *reinterpret_cast<__half2*>(&g_hh[(size_t)r * kF + c]) = x1h;
                        acc[i][j][2 * p] = acc[i][j][2 * p + 1] = 0.f;
                    }
        }

        __half* cs = smem + (kc % ST1) * STG12;
        mma_nt(cs, cs + BM * LDSA, acc, wm, wn, lane);

        if (pf < NCH) stsB_nt(psb + BM * LDSA, bb, tid);
    }

    // epilogue: read back own x1, apply silu, multiply by x2 (acc), store h
#pragma unroll
    for (int i = 0; i < 2; i++)
#pragma unroll
        for (int j = 0; j < 8; j++)
#pragma unroll
            for (int p = 0; p < 2; p++) {
                int r = rBase + i * 16 + p * 8;
                int c = cBase + j * 8;
                __half2* ptr = reinterpret_cast<__half2*>(&g_hh[(size_t)r * kF + c]);
                float2 x1f = __half22float2(*ptr);
                float s0 = x1f.x / (1.f + __expf(-x1f.x));
                float s1 = x1f.y / (1.f + __expf(-x1f.y));
                *ptr = __floats2half2_rn(s0 * acc[i][j][2 * p], s1 * acc[i][j][2 * p + 1]);
            }
}

// ==================== kernel 2: out = h @ w2 (NN) ====================
__global__ void __launch_bounds__(THREADS, 2) k_gemm3(const float* __restrict__ w2f,
                                                      float* __restrict__ out) {
    extern __shared__ __half smem[];
    const int tid = threadIdx.x, lane = tid & 31, warp = tid >> 5;
    const int wm = warp & 3, wn = warp >> 2;
    const int nt = blockIdx.x, mt = blockIdx.y, e = blockIdx.z;

    const __half* A = g_hh + (size_t)(e * kTPE + mt * BM) * kF;
    const float*  B = w2f + (size_t)e * kF * kH + nt * BN;
    constexpr int NCH = kF / BK;   // 64

    float acc[2][8][4];
#pragma unroll
    for (int i = 0; i < 2; i++)
#pragma unroll
        for (int j = 0; j < 8; j++)
#pragma unroll
            for (int r = 0; r < 4; r++) acc[i][j][r] = 0.f;

    float4 bb[8];
#pragma unroll
    for (int c = 0; c < ST3 - 1; c++) {
        __half* sb = smem + c * STG3;
        loadA(A, kF, c * BK, sb, tid);
        cp_commit();
        ldgB_nn(B, c * BK, bb, tid);
        stsB_nn(sb + BM * LDSA, bb, tid);
    }

    for (int kc = 0; kc < NCH; kc++) {
        cp_wait<ST3 - 2>();
        __syncthreads();
        const int pf = kc + ST3 - 1;
        __half* psb = smem + (pf % ST3) * STG3;
        if (pf < NCH) {
            loadA(A, kF, pf * BK, psb, tid);
            ldgB_nn(B, pf * BK, bb, tid);
        }
        cp_commit();
        __half* cs = smem + (kc % ST3) * STG3;
        mma_nn(cs, cs + BM * LDSA, acc, wm, wn, lane);
        if (pf < NCH) stsB_nn(psb + BM * LDSA, bb, tid);
    }

    const int rBase = e * kTPE + mt * BM + wm * 32 + (lane >> 2);
    const int cBase = nt * BN + wn * 64 + (lane & 3) * 2;
#pragma unroll
    for (int i = 0; i < 2; i++)
#pragma unroll
        for (int j = 0; j < 8; j++) {
            int r = rBase + i * 16;
            int c = cBase + j * 8;
            *reinterpret_cast<float2*>(&out[(size_t)r * kH + c]) =
                make_float2(acc[i][j][0], acc[i][j][1]);
            *reinterpret_cast<float2*>(&out[(size_t)(r + 8) * kH + c]) =
                make_float2(acc[i][j][2], acc[i][j][3]);
        }
}

// ---------------- launch ----------------
extern "C" void kernel_launch(void* const* d_in, const int* in_sizes, int n_in,
                              void* d_out, int out_size) {
    const float* x    = (const float*)d_in[0];
    const float* acts = (const float*)d_in[1];
    const float* wup  = (const float*)d_in[2];
    const float* v1   = (const float*)d_in[3];
    const float* w2   = (const float*)d_in[4];
    float* out = (float*)d_out;

    cudaFuncSetAttribute(k_gemm12, cudaFuncAttributeMaxDynamicSharedMemorySize, SMEM12);
    cudaFuncSetAttribute(k_gemm3,  cudaFuncAttributeMaxDynamicSharedMemorySize, SMEM3);

    k_cvt2<<<1184, 256>>>(x, acts);

    dim3 g12(kF / BN, kTPE / BM, kE);   // 32 x 8 x 8 = 2048 CTAs
    k_gemm12<<<g12, THREADS, SMEM12>>>(wup, v1);

    dim3 g3(kH / BN, kTPE / BM, kE);    // 8 x 8 x 8 = 512 CTAs
    k_gemm3<<<g3, THREADS, SMEM3>>>(w2, out);
}

// round 10
// speedup vs baseline: 1.3285x; 1.3285x over previous
#include <cuda_runtime.h>
#include <cuda_fp16.h>
#include <stdint.h>

// ---------------- problem constants ----------------
constexpr int kE   = 8;
constexpr int kH   = 1024;
constexpr int kF   = 4096;
constexpr int kDL  = 256;
constexpr int kTPE = 1024;
constexpr int kTok = kE * kTPE;   // 8192

// ---------------- tiling: 128x128 CTAs, 8 warps, 2 CTAs/SM ----------------
constexpr int BM = 128, BN = 128, BK = 64;
constexpr int THREADS = 256;      // 8 warps: 4 (M) x 2 (N), warp tile 32x64
constexpr int ST1 = 3;
constexpr int ST3 = 3;

constexpr int LDSA  = BK + 8;     // 72 halves per A row
constexpr int LDSB  = BK + 8;     // 72 halves per B row (NT: [n][k])
constexpr int LDSB3 = BN + 8;     // 136 halves per B row (NN: [k][n])

constexpr int STG12 = BM * LDSA + BN * LDSB;   // 18432 halves / stage
constexpr int STG3  = BM * LDSA + BK * LDSB3;  // 17920 halves / stage
constexpr int SMEM12 = ST1 * STG12 * 2;        // 110592 B (x2 CTA/SM)
constexpr int SMEM3  = ST3 * STG3  * 2;        // 107520 B (x2 CTA/SM)

// ---------------- fp16 scratch (device globals) ----------------
__device__ __half g_xh [(size_t)kTok * kH];        // 16 MB
__device__ __half g_ah [(size_t)kTok * kDL];       //  4 MB
__device__ __half g_wup[(size_t)kE * kF * kDL];    // 16 MB
__device__ __half g_v1 [(size_t)kE * kF * kH];     // 64 MB
__device__ __half g_w2 [(size_t)kE * kF * kH];     // 64 MB
__device__ __half g_hh [(size_t)kTok * kF];        // 64 MB  (silu(x1)*x2)

// ---------------- PTX helpers ----------------
__device__ __forceinline__ uint32_t smem_u32(const void* p) {
    uint32_t r;
    asm volatile("{ .reg .u64 t; cvta.to.shared.u64 t, %1; cvt.u32.u64 %0, t; }"
                 : "=r"(r) : "l"(p));
    return r;
}
__device__ __forceinline__ void cp16(uint32_t dst, const void* src) {
    asm volatile("cp.async.cg.shared.global [%0], [%1], 16;" :: "r"(dst), "l"(src));
}
__device__ __forceinline__ void cp_commit() { asm volatile("cp.async.commit_group;"); }
template <int N> __device__ __forceinline__ void cp_wait() {
    asm volatile("cp.async.wait_group %0;" :: "n"(N));
}
__device__ __forceinline__ void ldsm4(uint32_t* r, uint32_t a) {
    asm volatile("ldmatrix.sync.aligned.m8n8.x4.shared.b16 {%0,%1,%2,%3},[%4];"
                 : "=r"(r[0]), "=r"(r[1]), "=r"(r[2]), "=r"(r[3]) : "r"(a));
}
__device__ __forceinline__ void ldsm4t(uint32_t* r, uint32_t a) {
    asm volatile("ldmatrix.sync.aligned.m8n8.x4.trans.shared.b16 {%0,%1,%2,%3},[%4];"
                 : "=r"(r[0]), "=r"(r[1]), "=r"(r[2]), "=r"(r[3]) : "r"(a));
}
__device__ __forceinline__ void mma16816(float* c, const uint32_t* a, uint32_t b0, uint32_t b1) {
    asm volatile(
        "mma.sync.aligned.m16n8k16.row.col.f32.f16.f16.f32 "
        "{%0,%1,%2,%3},{%4,%5,%6,%7},{%8,%9},{%0,%1,%2,%3};"
        : "+f"(c[0]), "+f"(c[1]), "+f"(c[2]), "+f"(c[3])
        : "r"(a[0]), "r"(a[1]), "r"(a[2]), "r"(a[3]), "r"(b0), "r"(b1));
}

// ---------------- fused fp32 -> fp16 conversion (one launch, streaming) ----------------
__global__ void k_cvt_all(const float* __restrict__ x, const float* __restrict__ a,
                          const float* __restrict__ wu, const float* __restrict__ v,
                          const float* __restrict__ w) {
    constexpr size_t N1 = (size_t)kTok * kH / 4, N2 = (size_t)kTok * kDL / 4,
                     N3 = (size_t)kE * kF * kDL / 4, N4 = (size_t)kE * kF * kH / 4;
    constexpr size_t C1 = N1, C2 = C1 + N2, C3 = C2 + N3, C4 = C3 + N4, C5 = C4 + N4;
    for (size_t i = (size_t)blockIdx.x * blockDim.x + threadIdx.x; i < C5;
         i += (size_t)gridDim.x * blockDim.x) {
        const float4* s; uint2* d; size_t o;
        if      (i < C1) { s = (const float4*)x;  d = (uint2*)g_xh;  o = i;      }
        else if (i < C2) { s = (const float4*)a;  d = (uint2*)g_ah;  o = i - C1; }
        else if (i < C3) { s = (const float4*)wu; d = (uint2*)g_wup; o = i - C2; }
        else if (i < C4) { s = (const float4*)v;  d = (uint2*)g_v1;  o = i - C3; }
        else             { s = (const float4*)w;  d = (uint2*)g_w2;  o = i - C4; }
        float4 t = __ldcs(&s[o]);
        __half2 h0 = __floats2half2_rn(t.x, t.y);
        __half2 h1 = __floats2half2_rn(t.z, t.w);
        uint2 pk = make_uint2(*reinterpret_cast<uint32_t*>(&h0),
                              *reinterpret_cast<uint32_t*>(&h1));
        __stcs(&d[o], pk);
    }
}

// ---------------- tile loaders (cp.async, 16B vectors, 256 threads) ----------------
__device__ __forceinline__ void load_nt(const __half* gA, int ldA, const __half* gB, int ldB,
                                        int kBase, __half* sA, __half* sB, int tid) {
#pragma unroll
    for (int i = 0; i < 4; i++) {
        int v = tid + i * THREADS;
        int row = v >> 3, c = (v & 7) * 8;
        cp16(smem_u32(sA + row * LDSA + c), gA + (size_t)row * ldA + kBase + c);
    }
#pragma unroll
    for (int i = 0; i < 4; i++) {
        int v = tid + i * THREADS;
        int row = v >> 3, c = (v & 7) * 8;
        cp16(smem_u32(sB + row * LDSB + c), gB + (size_t)row * ldB + kBase + c);
    }
}

__device__ __forceinline__ void load_nn(const __half* gA, int ldA, const __half* gB, int ldB,
                                        int kBase, __half* sA, __half* sB, int tid) {
#pragma unroll
    for (int i = 0; i < 4; i++) {
        int v = tid + i * THREADS;
        int row = v >> 3, c = (v & 7) * 8;
        cp16(smem_u32(sA + row * LDSA + c), gA + (size_t)row * ldA + kBase + c);
    }
#pragma unroll
    for (int i = 0; i < 4; i++) {
        int v = tid + i * THREADS;
        int row = v >> 4, c = (v & 15) * 8;
        cp16(smem_u32(sB + row * LDSB3 + c), gB + (size_t)(kBase + row) * ldB + c);
    }
}

// ---------- lookahead-2 software-pipelined warp-tile MMA (32x64), NT ----------
__device__ __forceinline__ void mma_nt(const __half* sA, const __half* sB,
                                       float (&acc)[2][8][4], int wm, int wn, int lane) {
    const uint32_t aAddr = smem_u32(sA + (wm * 32 + (lane & 15)) * LDSA + (lane >> 4) * 8);
    const uint32_t bAddr = smem_u32(sB + (wn * 64 + (lane & 7) + ((lane >> 4) << 3)) * LDSB
                                       + ((lane >> 3) & 1) * 8);
    // step s = k*4 + j; B(s) at bAddr + (s>>2)*32 + (s&3)*16*LDSB*2
    uint32_t a_cur[2][4], a_nxt[2][4], b[3][4];
    ldsm4(a_cur[0], aAddr);
    ldsm4(a_cur[1], aAddr + 16 * LDSA * 2);
    ldsm4(b[0], bAddr);
    ldsm4(b[1], bAddr + 16 * LDSB * 2);
#pragma unroll
    for (int s = 0; s < 16; s++) {
        const int j = s & 3, k = s >> 2;
        if (s + 2 < 16) {
            const int s2 = s + 2;
            ldsm4(b[s2 % 3], bAddr + (s2 >> 2) * 32 + (s2 & 3) * 16 * LDSB * 2);
        }
        if (j == 2 && k < 3) {
            ldsm4(a_nxt[0], aAddr + (k + 1) * 32);
            ldsm4(a_nxt[1], aAddr + (k + 1) * 32 + 16 * LDSA * 2);
        }
        const uint32_t* bc = b[s % 3];
        mma16816(acc[0][2 * j],     a_cur[0], bc[0], bc[1]);
        mma16816(acc[1][2 * j],     a_cur[1], bc[0], bc[1]);
        mma16816(acc[0][2 * j + 1], a_cur[0], bc[2], bc[3]);
        mma16816(acc[1][2 * j + 1], a_cur[1], bc[2], bc[3]);
        if (j == 3 && k < 3) {
#pragma unroll
            for (int im = 0; im < 2; im++)
#pragma unroll
                for (int r = 0; r < 4; r++) a_cur[im][r] = a_nxt[im][r];
        }
    }
}

// ---------- lookahead-2 software-pipelined warp-tile MMA (32x64), NN ----------
__device__ __forceinline__ void mma_nn(const __half* sA, const __half* sB,
                                       float (&acc)[2][8][4], int wm, int wn, int lane) {
    const uint32_t aAddr = smem_u32(sA + (wm * 32 + (lane & 15)) * LDSA + (lane >> 4) * 8);
    const uint32_t bAddr = smem_u32(sB + ((lane & 7) + ((lane >> 3) & 1) * 8) * LDSB3
                                       + wn * 64 + (lane >> 4) * 8);
    // step s = k*4 + j; B(s) at bAddr + (s>>2)*16*LDSB3*2 + (s&3)*32
    uint32_t a_cur[2][4], a_nxt[2][4], b[3][4];
    ldsm4(a_cur[0], aAddr);
    ldsm4(a_cur[1], aAddr + 16 * LDSA * 2);
    ldsm4t(b[0], bAddr);
    ldsm4t(b[1], bAddr + 32);
#pragma unroll
    for (int s = 0; s < 16; s++) {
        const int j = s & 3, k = s >> 2;
        if (s + 2 < 16) {
            const int s2 = s + 2;
            ldsm4t(b[s2 % 3], bAddr + (s2 >> 2) * 16 * LDSB3 * 2 + (s2 & 3) * 32);
        }
        if (j == 2 && k < 3) {
            ldsm4(a_nxt[0], aAddr + (k + 1) * 32);
            ldsm4(a_nxt[1], aAddr + (k + 1) * 32 + 16 * LDSA * 2);
        }
        const uint32_t* bc = b[s % 3];
        mma16816(acc[0][2 * j],     a_cur[0], bc[0], bc[1]);
        mma16816(acc[1][2 * j],     a_cur[1], bc[0], bc[1]);
        mma16816(acc[0][2 * j + 1], a_cur[0], bc[2], bc[3]);
        mma16816(acc[1][2 * j + 1], a_cur[1], bc[2], bc[3]);
        if (j == 3 && k < 3) {
#pragma unroll
            for (int im = 0; im < 2; im++)
#pragma unroll
                for (int r = 0; r < 4; r++) a_cur[im][r] = a_nxt[im][r];
        }
    }
}

// ==================== kernel 1: x1=acts@wup^T, x2=x@v1^T, h=silu(x1)*x2 ===========
__global__ void __launch_bounds__(THREADS, 2) k_gemm12() {
    extern __shared__ __half smem[];
    const int tid = threadIdx.x, lane = tid & 31, warp = tid >> 5;
    const int wm = warp & 3, wn = warp >> 2;
    const int nt = blockIdx.x, mt = blockIdx.y, e = blockIdx.z;

    const __half* A1 = g_ah  + (size_t)(e * kTPE + mt * BM) * kDL;
    const __half* B1 = g_wup + ((size_t)e * kF + nt * BN) * kDL;
    const __half* A2 = g_xh  + (size_t)(e * kTPE + mt * BM) * kH;
    const __half* B2 = g_v1  + ((size_t)e * kF + nt * BN) * kH;

    constexpr int NCH1 = kDL / BK;          // 4
    constexpr int NCH  = NCH1 + kH / BK;    // 20

    auto srcOf = [&](int c, const __half*& A, const __half*& B, int& la, int& lb, int& ko) {
        if (c < NCH1) { A = A1; B = B1; la = kDL; lb = kDL; ko = c * BK; }
        else          { A = A2; B = B2; la = kH;  lb = kH;  ko = (c - NCH1) * BK; }
    };

    float acc[2][8][4];
#pragma unroll
    for (int i = 0; i < 2; i++)
#pragma unroll
        for (int j = 0; j < 8; j++)
#pragma unroll
            for (int r = 0; r < 4; r++) acc[i][j][r] = 0.f;
    __half2 sf[2][8][2];

#pragma unroll
    for (int c = 0; c < ST1 - 1; c++) {
        const __half *A, *B; int la, lb, ko;
        srcOf(c, A, B, la, lb, ko);
        __half* sb = smem + c * STG12;
        load_nt(A, la, B, lb, ko, sb, sb + BM * LDSA, tid);
        cp_commit();
    }

    for (int kc = 0; kc < NCH; kc++) {
        cp_wait<ST1 - 2>();
        __syncthreads();
        const int pf = kc + ST1 - 1;
        if (pf < NCH) {
            const __half *A, *B; int la, lb, ko;
            srcOf(pf, A, B, la, lb, ko);
            __half* sb = smem + (pf % ST1) * STG12;
            load_nt(A, la, B, lb, ko, sb, sb + BM * LDSA, tid);
        }
        cp_commit();

        if (kc == NCH1) {
#pragma unroll
            for (int i = 0; i < 2; i++)
#pragma unroll
                for (int j = 0; j < 8; j++) {
#pragma unroll
                    for (int p = 0; p < 2; p++) {
                        float x0 = acc[i][j][2 * p], x1 = acc[i][j][2 * p + 1];
                        sf[i][j][p] = __floats2half2_rn(x0 / (1.f + __expf(-x0)),
                                                        x1 / (1.f + __expf(-x1)));
                    }
                    acc[i][j][0] = acc[i][j][1] = acc[i][j][2] = acc[i][j][3] = 0.f;
                }
        }

        __half* cs = smem + (kc % ST1) * STG12;
        mma_nt(cs, cs + BM * LDSA, acc, wm, wn, lane);
    }

    const int rBase = e * kTPE + mt * BM + wm * 32 + (lane >> 2);
    const int cBase = nt * BN + wn * 64 + (lane & 3) * 2;
#pragma unroll
    for (int i = 0; i < 2; i++)
#pragma unroll
        for (int j = 0; j < 8; j++) {
            int r = rBase + i * 16;
            int c = cBase + j * 8;
            float2 s0 = __half22float2(sf[i][j][0]);
            float2 s1 = __half22float2(sf[i][j][1]);
            __half2 h0 = __floats2half2_rn(s0.x * acc[i][j][0], s0.y * acc[i][j][1]);
            __half2 h1 = __floats2half2_rn(s1.x * acc[i][j][2], s1.y * acc[i][j][3]);
            *reinterpret_cast<__half2*>(&g_hh[(size_t)r * kF + c])       = h0;
            *reinterpret_cast<__half2*>(&g_hh[(size_t)(r + 8) * kF + c]) = h1;
        }
}

// ==================== kernel 2: out = h @ w2 (NN) ====================
__global__ void __launch_bounds__(THREADS, 2) k_gemm3(float* __restrict__ out) {
    extern __shared__ __half smem[];
    const int tid = threadIdx.x, lane = tid & 31, warp = tid >> 5;
    const int wm = warp & 3, wn = warp >> 2;
    const int nt = blockIdx.x, mt = blockIdx.y, e = blockIdx.z;

    const __half* A = g_hh + (size_t)(e * kTPE + mt * BM) * kF;
    const __half* B = g_w2 + (size_t)e * kF * kH + nt * BN;
    constexpr int NCH = kF / BK;   // 64

    float acc[2][8][4];
#pragma unroll
    for (int i = 0; i < 2; i++)
#pragma unroll
        for (int j = 0; j < 8; j++)
#pragma unroll
            for (int r = 0; r < 4; r++) acc[i][j][r] = 0.f;

#pragma unroll
    for (int c = 0; c < ST3 - 1; c++) {
        __half* sb = smem + c * STG3;
        load_nn(A, kF, B, kH, c * BK, sb, sb + BM * LDSA, tid);
        cp_commit();
    }

    for (int kc = 0; kc < NCH; kc++) {
        cp_wait<ST3 - 2>();
        __syncthreads();
        const int pf = kc + ST3 - 1;
        if (pf < NCH) {
            __half* sb = smem + (pf % ST3) * STG3;
            load_nn(A, kF, B, kH, pf * BK, sb, sb + BM * LDSA, tid);
        }
        cp_commit();
        __half* cs = smem + (kc % ST3) * STG3;
        mma_nn(cs, cs + BM * LDSA, acc, wm, wn, lane);
    }

    const int rBase = e * kTPE + mt * BM + wm * 32 + (lane >> 2);
    const int cBase = nt * BN + wn * 64 + (lane & 3) * 2;
#pragma unroll
    for (int i = 0; i < 2; i++)
#pragma unroll
        for (int j = 0; j < 8; j++) {
            int r = rBase + i * 16;
            int c = cBase + j * 8;
            *reinterpret_cast<float2*>(&out[(size_t)r * kH + c]) =
                make_float2(acc[i][j][0], acc[i][j][1]);
            *reinterpret_cast<float2*>(&out[(size_t)(r + 8) * kH + c]) =
                make_float2(acc[i][j][2], acc[i][j][3]);
        }
}

// ---------------- launch ----------------
extern "C" void kernel_launch(void* const* d_in, const int* in_sizes, int n_in,
                              void* d_out, int out_size) {
    const float* x    = (const float*)d_in[0];
    const float* acts = (const float*)d_in[1];
    const float* wup  = (const float*)d_in[2];
    const float* v1   = (const float*)d_in[3];
    const float* w2   = (const float*)d_in[4];
    float* out = (float*)d_out;

    cudaFuncSetAttribute(k_gemm12, cudaFuncAttributeMaxDynamicSharedMemorySize, SMEM12);
    cudaFuncSetAttribute(k_gemm3,  cudaFuncAttributeMaxDynamicSharedMemorySize, SMEM3);

    k_cvt_all<<<1184, 256>>>(x, acts, wup, v1, w2);

    dim3 g12(kF / BN, kTPE / BM, kE);   // 32 x 8 x 8 = 2048 CTAs
    k_gemm12<<<g12, THREADS, SMEM12>>>();

    dim3 g3(kH / BN, kTPE / BM, kE);    // 8 x 8 x 8 = 512 CTAs
    k_gemm3<<<g3, THREADS, SMEM3>>>(out);
}